// round 1
// baseline (speedup 1.0000x reference)
#include <cuda_runtime.h>
#include <math.h>
#include <stdint.h>

#define DD 1536
#define SS 1024
#define BB 4
#define NROWS (BB*SS)        // 4096
#define MB (BB*(SS-1))       // 4092
#define K2D (2*DD)           // 3072
#define QKVN (3*DD)          // 4608
#define HH 12
#define HDIM 128

// ---------------- scratch (device globals; no allocations allowed) ----------------
__device__ float g_xling[NROWS*DD];
__device__ float g_norms[NROWS];
__device__ float g_cs[BB*(1023+511+255)];
__device__ float g_base[MB];
__device__ float g_learned[MB];
__device__ float g_final[MB];
__device__ int   g_seg[NROWS];
__device__ int   g_segstart[NROWS];
__device__ int   g_segend[NROWS];
__device__ int   g_cstart[BB*257];
__device__ float g_bi[(size_t)MB*K2D];
__device__ float g_h1[(size_t)MB*DD];
__device__ float g_h2[(size_t)MB*768];
__device__ float g_qkv[(size_t)NROWS*QKVN];
__device__ float g_ctx[(size_t)NROWS*DD];
__device__ float g_attnout[(size_t)NROWS*DD];
__device__ float g_chunk[(size_t)BB*256*DD];
__device__ float g_hproc[(size_t)BB*256*K2D];

// ---------------- helpers ----------------
__device__ __forceinline__ float gelu_f(float v){
    return 0.5f*v*(1.0f + erff(v*0.7071067811865475f));
}

__device__ __forceinline__ float block_reduce_sum(float v){
    __shared__ float sbuf[32];
    int lane = threadIdx.x & 31, wid = threadIdx.x >> 5;
    #pragma unroll
    for (int o=16;o>0;o>>=1) v += __shfl_xor_sync(0xffffffffu, v, o);
    __syncthreads();                 // protect sbuf across repeated calls
    if (lane==0) sbuf[wid] = v;
    __syncthreads();
    float r = 0.0f;
    if (threadIdx.x < (blockDim.x >> 5)) r = sbuf[threadIdx.x];
    if (wid==0){
        #pragma unroll
        for (int o=16;o>0;o>>=1) r += __shfl_xor_sync(0xffffffffu, r, o);
    }
    return r;   // valid in warp 0
}

// ---------------- generic fp32 GEMM: C = act(A[M,K] @ W[N,K]^T + bias) ----------------
template<int ACT>
__global__ __launch_bounds__(256) void gemm_kernel(
    const float* __restrict__ A, const float* __restrict__ W,
    const float* __restrict__ bias, float* __restrict__ C,
    int M, int N, int K)
{
    __shared__ float As[16][68];
    __shared__ float Bs[16][68];
    const int tid = threadIdx.x;
    const int bm = blockIdx.y*64, bn = blockIdx.x*64;
    const int tx = tid & 15, ty = tid >> 4;
    const int lr = tid >> 2, lk = (tid & 3) << 2;

    float acc[4][4] = {};
    const int am = bm + lr;
    const bool avalid = (am < M);
    const float* Aptr = A + (size_t)(avalid ? am : 0)*K + lk;
    const float* Wptr = W + (size_t)(bn+lr)*K + lk;

    for (int k0 = 0; k0 < K; k0 += 16){
        float4 av = avalid ? *(const float4*)(Aptr + k0) : make_float4(0,0,0,0);
        float4 bv = *(const float4*)(Wptr + k0);
        As[lk+0][lr]=av.x; As[lk+1][lr]=av.y; As[lk+2][lr]=av.z; As[lk+3][lr]=av.w;
        Bs[lk+0][lr]=bv.x; Bs[lk+1][lr]=bv.y; Bs[lk+2][lr]=bv.z; Bs[lk+3][lr]=bv.w;
        __syncthreads();
        #pragma unroll
        for (int kk=0; kk<16; kk++){
            float4 a = *(const float4*)&As[kk][ty*4];
            float4 b = *(const float4*)&Bs[kk][tx*4];
            float ar[4] = {a.x,a.y,a.z,a.w};
            float br[4] = {b.x,b.y,b.z,b.w};
            #pragma unroll
            for (int i=0;i<4;i++)
                #pragma unroll
                for (int j=0;j<4;j++)
                    acc[i][j] += ar[i]*br[j];
        }
        __syncthreads();
    }

    float4 bb = *(const float4*)(bias + bn + tx*4);
    float bbv[4] = {bb.x, bb.y, bb.z, bb.w};
    #pragma unroll
    for (int i=0;i<4;i++){
        int row = bm + ty*4 + i;
        if (row < M){
            float o[4];
            #pragma unroll
            for (int j=0;j<4;j++){
                float v = acc[i][j] + bbv[j];
                if (ACT==1) v = gelu_f(v);
                o[j] = v;
            }
            *(float4*)(C + (size_t)row*N + bn + tx*4) = make_float4(o[0],o[1],o[2],o[3]);
        }
    }
}

// ---------------- stage kernels ----------------
__global__ void norms_kernel(const float* __restrict__ xling, float* __restrict__ norms){
    int row = blockIdx.x;
    const float4* p = (const float4*)(xling + (size_t)row*DD);
    float s = 0.f;
    for (int d = threadIdx.x; d < DD/4; d += blockDim.x){
        float4 v = p[d];
        s += v.x*v.x + v.y*v.y + v.z*v.z + v.w*v.w;
    }
    s = block_reduce_sum(s);
    if (threadIdx.x == 0) norms[row] = fmaxf(sqrtf(s), 1e-8f);
}

__global__ void cs_kernel(const float* __restrict__ xling, const float* __restrict__ norms,
                          float* __restrict__ out, int scale, int Lin){
    int idx = blockIdx.x;
    int b = idx / Lin, t = idx % Lin;
    int r0 = b*SS + t*scale, r1 = r0 + scale;
    const float4* a = (const float4*)(xling + (size_t)r0*DD);
    const float4* c = (const float4*)(xling + (size_t)r1*DD);
    float s = 0.f;
    for (int d = threadIdx.x; d < DD/4; d += blockDim.x){
        float4 va = a[d], vc = c[d];
        s += va.x*vc.x + va.y*vc.y + va.z*vc.z + va.w*vc.w;
    }
    s = block_reduce_sum(s);
    if (threadIdx.x == 0) out[idx] = s / (norms[r0]*norms[r1]);
}

__global__ void base_kernel(const float* __restrict__ cs, float* __restrict__ base){
    int i = blockIdx.x*blockDim.x + threadIdx.x;
    if (i >= MB) return;
    int b = i / 1023, t = i % 1023;
    const int Lins[3] = {1023, 511, 255};
    const int offs[3] = {0, BB*1023, BB*1023 + BB*511};
    float sum = 0.f;
    #pragma unroll
    for (int j=0;j<3;j++){
        int Lin = Lins[j];
        float ratio = (float)((double)Lin / 1023.0);
        float src = ((float)t + 0.5f)*ratio - 0.5f;
        src = fminf(fmaxf(src, 0.0f), (float)(Lin-1));
        int i0 = (int)floorf(src);
        int i1 = min(i0+1, Lin-1);
        float w = src - (float)i0;
        const float* c = cs + offs[j] + b*Lin;
        sum += c[i0]*(1.0f-w) + c[i1]*w;
    }
    base[i] = 0.5f*(1.0f - sum/3.0f);
}

__global__ void bi_kernel(const float* __restrict__ x, float* __restrict__ bi){
    int i = blockIdx.x*blockDim.x + threadIdx.x;   // float4 index
    const int total = MB*(K2D/4);
    if (i >= total) return;
    int row = i / (K2D/4);
    int k4 = (i % (K2D/4))*4;
    int b = row / 1023, s = row % 1023;
    const float* src = (k4 < DD) ? (x + (size_t)(b*SS+s)*DD + k4)
                                 : (x + (size_t)(b*SS+s+1)*DD + (k4-DD));
    *(float4*)(bi + (size_t)row*K2D + k4) = *(const float4*)src;
}

__global__ void learned_kernel(const float* __restrict__ h2, const float* __restrict__ W3,
                               const float* __restrict__ b3, int n, float* __restrict__ learned){
    int row = blockIdx.x;
    const float* hr = h2 + (size_t)row*768;
    const float* w  = W3 + n*768;
    float s = 0.f;
    for (int j = threadIdx.x; j < 768; j += blockDim.x) s += hr[j]*w[j];
    s = block_reduce_sum(s);
    if (threadIdx.x == 0){
        float v = 1.0f/(1.0f + expf(-(s + b3[n])));
        learned[row] += v;
    }
}

__global__ void final_kernel(const float* __restrict__ base, const float* __restrict__ learned,
                             float* __restrict__ fin){
    int i = blockIdx.x*blockDim.x + threadIdx.x;
    if (i >= MB) return;
    fin[i] = 0.6f*base[i] + 0.4f*(learned[i]/3.0f);
}

__global__ void seg_kernel(const float* __restrict__ fin, int* __restrict__ seg,
                           int* __restrict__ segst, int* __restrict__ segen,
                           int* __restrict__ cstart){
    int b = threadIdx.x;
    if (b >= BB) return;
    int cur = 0;
    seg[b*SS] = 0;
    for (int i=1;i<SS;i++){
        if (fin[b*1023 + i-1] > 0.5f) cur++;
        seg[b*SS + i] = cur;
    }
    for (int m=0;m<257;m++) cstart[b*257+m] = SS;
    int st = 0;
    for (int s=0;s<SS;s++){
        int sg = seg[b*SS+s];
        if (s==0 || sg != seg[b*SS+s-1]){
            st = s;
            if (sg < 257) cstart[b*257+sg] = s;
        }
        segst[b*SS+s] = st;
    }
    int en = SS;
    for (int s=SS-1;s>=0;s--){
        if (s==SS-1 || seg[b*SS+s] != seg[b*SS+s+1]) en = s+1;
        segen[b*SS+s] = en;
    }
}

__global__ void attn_kernel(const float* __restrict__ qkv, const int* __restrict__ segst,
                            const int* __restrict__ segen, float* __restrict__ ctx){
    int gw = (blockIdx.x*blockDim.x + threadIdx.x) >> 5;
    int lane = threadIdx.x & 31;
    if (gw >= BB*SS*HH) return;
    int h = gw % HH; int q = (gw/HH) % SS; int b = gw/(HH*SS);
    int rq = b*SS + q;
    float4 qv = *(const float4*)(qkv + (size_t)rq*QKVN + h*HDIM + lane*4);
    int st = segst[rq], en = segen[rq];
    float m = -3.0e38f, l = 0.0f;
    float ax=0.f, ay=0.f, az=0.f, aw=0.f;
    for (int k=st;k<en;k++){
        const float* kp = qkv + (size_t)(b*SS+k)*QKVN + DD + h*HDIM + lane*4;
        float4 kv = *(const float4*)kp;
        float s = qv.x*kv.x + qv.y*kv.y + qv.z*kv.z + qv.w*kv.w;
        #pragma unroll
        for (int o=16;o>0;o>>=1) s += __shfl_xor_sync(0xffffffffu, s, o);
        s *= 0.08838834764831845f;   // 1/sqrt(128)
        float mn = fmaxf(m, s);
        float corr = expf(m - mn);
        float p = expf(s - mn);
        const float* vp = qkv + (size_t)(b*SS+k)*QKVN + 2*DD + h*HDIM + lane*4;
        float4 vv = *(const float4*)vp;
        ax = ax*corr + p*vv.x;
        ay = ay*corr + p*vv.y;
        az = az*corr + p*vv.z;
        aw = aw*corr + p*vv.w;
        l = l*corr + p;
        m = mn;
    }
    float inv = 1.0f/l;
    *(float4*)(ctx + (size_t)rq*DD + h*HDIM + lane*4) = make_float4(ax*inv, ay*inv, az*inv, aw*inv);
}

__global__ void chunk_kernel(const float* __restrict__ attnout, const int* __restrict__ cstart,
                             const float* __restrict__ size_emb, const float* __restrict__ pos_enc,
                             float* __restrict__ chunk){
    int bm = blockIdx.x;
    int b = bm >> 8, m = bm & 255;
    int st = cstart[b*257+m], en = cstart[b*257+m+1];
    int cnt = en - st;
    int clen = min(cnt, 1023);
    float denom = fmaxf((float)cnt, 1.0f);
    for (int d = threadIdx.x; d < DD; d += blockDim.x){
        float s = 0.f;
        for (int r=st; r<en; r++) s += attnout[(size_t)(b*SS+r)*DD + d];
        float v = (cnt > 0) ? (s/denom + size_emb[(size_t)clen*DD + d]) : 0.0f;
        chunk[(size_t)bm*DD + d] = v + pos_enc[(size_t)m*DD + d];
    }
}

__global__ void ln_kernel(float* __restrict__ y, const float* __restrict__ g,
                          const float* __restrict__ bta){
    int row = blockIdx.x;
    float* yr = y + (size_t)row*DD;
    __shared__ float stats[2];
    float s = 0.f;
    for (int d = threadIdx.x; d < DD; d += blockDim.x) s += yr[d];
    s = block_reduce_sum(s);
    if (threadIdx.x == 0) stats[0] = s / (float)DD;
    __syncthreads();
    float mu = stats[0];
    float v = 0.f;
    for (int d = threadIdx.x; d < DD; d += blockDim.x){
        float t = yr[d] - mu; v += t*t;
    }
    v = block_reduce_sum(v);
    if (threadIdx.x == 0) stats[1] = 1.0f/sqrtf(v/(float)DD + 1e-5f);
    __syncthreads();
    float inv = stats[1];
    for (int d = threadIdx.x; d < DD; d += blockDim.x)
        yr[d] = (yr[d] - mu)*inv*g[d] + bta[d];
}

// ---------------- launch ----------------
static void gemm(const float* A, const float* W, const float* bias, float* C,
                 int M, int N, int K, int act){
    dim3 grid(N/64, (M+63)/64);
    if (act) gemm_kernel<1><<<grid, 256>>>(A, W, bias, C, M, N, K);
    else     gemm_kernel<0><<<grid, 256>>>(A, W, bias, C, M, N, K);
}

extern "C" void kernel_launch(void* const* d_in, const int* in_sizes, int n_in,
                              void* d_out, int out_size){
    const float* x        = (const float*)d_in[0];
    const float* Wp       = (const float*)d_in[1];
    const float* bp       = (const float*)d_in[2];
    const float* detW1    = (const float*)d_in[3];
    const float* detb1    = (const float*)d_in[4];
    const float* detW2    = (const float*)d_in[5];
    const float* detb2    = (const float*)d_in[6];
    const float* detW3    = (const float*)d_in[7];
    const float* detb3    = (const float*)d_in[8];
    const float* in_proj_w= (const float*)d_in[9];
    const float* in_proj_b= (const float*)d_in[10];
    const float* out_w    = (const float*)d_in[11];
    const float* out_b    = (const float*)d_in[12];
    const float* size_emb = (const float*)d_in[13];
    const float* pos_enc  = (const float*)d_in[14];
    const float* procW1   = (const float*)d_in[15];
    const float* procb1   = (const float*)d_in[16];
    const float* procW2   = (const float*)d_in[17];
    const float* procb2   = (const float*)d_in[18];
    const float* ln_g     = (const float*)d_in[19];
    const float* ln_b     = (const float*)d_in[20];
    float* out = (float*)d_out;

    float *xling,*norms,*cs,*base,*learned,*finalp,*bi,*h1,*h2,*qkv,*ctx,*attnout,*chunk,*hproc;
    int *seg,*segst,*segen,*cstart;
    cudaGetSymbolAddress((void**)&xling,   g_xling);
    cudaGetSymbolAddress((void**)&norms,   g_norms);
    cudaGetSymbolAddress((void**)&cs,      g_cs);
    cudaGetSymbolAddress((void**)&base,    g_base);
    cudaGetSymbolAddress((void**)&learned, g_learned);
    cudaGetSymbolAddress((void**)&finalp,  g_final);
    cudaGetSymbolAddress((void**)&bi,      g_bi);
    cudaGetSymbolAddress((void**)&h1,      g_h1);
    cudaGetSymbolAddress((void**)&h2,      g_h2);
    cudaGetSymbolAddress((void**)&qkv,     g_qkv);
    cudaGetSymbolAddress((void**)&ctx,     g_ctx);
    cudaGetSymbolAddress((void**)&attnout, g_attnout);
    cudaGetSymbolAddress((void**)&chunk,   g_chunk);
    cudaGetSymbolAddress((void**)&hproc,   g_hproc);
    cudaGetSymbolAddress((void**)&seg,     g_seg);
    cudaGetSymbolAddress((void**)&segst,   g_segstart);
    cudaGetSymbolAddress((void**)&segen,   g_segend);
    cudaGetSymbolAddress((void**)&cstart,  g_cstart);

    // 1) x_ling = x @ Wp^T + bp
    gemm(x, Wp, bp, xling, NROWS, DD, DD, 0);

    // 2) multi-scale cosine boundary base
    norms_kernel<<<NROWS, 128>>>(xling, norms);
    cs_kernel<<<BB*1023, 128>>>(xling, norms, cs,                     1, 1023);
    cs_kernel<<<BB*511,  128>>>(xling, norms, cs + BB*1023,           2, 511);
    cs_kernel<<<BB*255,  128>>>(xling, norms, cs + BB*1023 + BB*511,  4, 255);
    base_kernel<<<(MB+255)/256, 256>>>(cs, base);

    // 3) learned boundary detector (3 MLPs)
    bi_kernel<<<(MB*(K2D/4)+255)/256, 256>>>(x, bi);
    cudaMemsetAsync(learned, 0, MB*sizeof(float));
    for (int n=0;n<3;n++){
        gemm(bi, detW1 + (size_t)n*DD*K2D, detb1 + n*DD,  h1, MB, DD,  K2D, 1);
        gemm(h1, detW2 + (size_t)n*768*DD, detb2 + n*768, h2, MB, 768, DD,  1);
        learned_kernel<<<MB, 256>>>(h2, detW3, detb3, n, learned);
    }
    final_kernel<<<(MB+255)/256, 256>>>(base, learned, finalp);

    // 4) segmentation (serial per-batch cumsum + range tables)
    seg_kernel<<<1, 4>>>(finalp, seg, segst, segen, cstart);

    // 5) attention (segment-masked == contiguous-range flash attention)
    gemm(x, in_proj_w, in_proj_b, qkv, NROWS, QKVN, DD, 0);
    attn_kernel<<<(NROWS*HH*32 + 127)/128, 128>>>(qkv, segst, segen, ctx);
    gemm(ctx, out_w, out_b, attnout, NROWS, DD, DD, 0);

    // 6) segment pooling -> chunks
    chunk_kernel<<<BB*256, 256>>>(attnout, cstart, size_emb, pos_enc, chunk);

    // 7) chunk processor MLP + layernorm
    gemm(chunk, procW1, procb1, hproc, BB*256, K2D, DD, 1);
    gemm(hproc, procW2, procb2, out,   BB*256, DD,  K2D, 0);
    ln_kernel<<<BB*256, 256>>>(out, ln_g, ln_b);
}